// round 2
// baseline (speedup 1.0000x reference)
#include <cuda_runtime.h>

#define NG  8     // graphs
#define NN  128   // nodes
#define DIM 128   // embedding dim
#define NE  128   // edge types
#define VEC 300   // word-vec dim
#define CHM 8     // k-chunk per double-buffer stage (float4 per k)

// ---- scratch (device globals; no allocations allowed) ----
__device__ __align__(16) float g_base[NN][DIM];
__device__ __align__(16) float g_vacc[NG][NN][DIM];
__device__ __align__(16) float g_bvec[NG][NN][DIM];
__device__ int   g_parent[NG][NN];
__device__ int   g_ccount[NG][NN];
__device__ int   g_cdone[NG][NN];
__device__ int   g_onpath[NG][NN];
__device__ int   g_path[NG][NN];
__device__ int   g_plen[NG];
__device__ int   g_edges_eff[NN];
__device__ float g_dscore;
__device__ int   g_taskctr;

// ---------------------------------------------------------------------------
// Streaming matvec: thread owns 4 consecutive output dims (d0 = 4*lane).
// W4 points at W[0][d0] (row stride DIM floats = DIM/4 float4).
// Double-buffered register chunks -> ~16 LDG.128 in flight per thread.
// m accumulates: m[j] += sum_k r[k] * W[k][d0+j].
// ---------------------------------------------------------------------------
template<int K>
__device__ __forceinline__ void mv_stream(const float4* __restrict__ W4,
                                          const float* __restrict__ r,
                                          float4& m) {
    constexpr int STEP = 2 * CHM;
    constexpr int NCH  = (K + STEP - 1) / STEP;
    float4 A[CHM], B[CHM];
#pragma unroll
    for (int i = 0; i < CHM; ++i)
        A[i] = (i < K) ? W4[i * (DIM / 4)] : make_float4(0.f, 0.f, 0.f, 0.f);
#pragma unroll
    for (int o = 0; o < NCH; ++o) {
        const int kb = o * STEP, k2 = kb + CHM, k3 = kb + STEP;
#pragma unroll
        for (int i = 0; i < CHM; ++i)
            B[i] = (k2 + i < K) ? W4[(k2 + i) * (DIM / 4)] : make_float4(0.f, 0.f, 0.f, 0.f);
#pragma unroll
        for (int i = 0; i < CHM; ++i)
            if (kb + i < K) {
                const float rk = r[kb + i];
                m.x += rk * A[i].x; m.y += rk * A[i].y;
                m.z += rk * A[i].z; m.w += rk * A[i].w;
            }
#pragma unroll
        for (int i = 0; i < CHM; ++i)
            A[i] = (k3 + i < K) ? W4[(k3 + i) * (DIM / 4)] : make_float4(0.f, 0.f, 0.f, 0.f);
#pragma unroll
        for (int i = 0; i < CHM; ++i)
            if (k2 + i < K) {
                const float rk = r[k2 + i];
                m.x += rk * B[i].x; m.y += rk * B[i].y;
                m.z += rk * B[i].z; m.w += rk * B[i].w;
            }
    }
}

__device__ __forceinline__ float warp_sum(float s) {
#pragma unroll
    for (int o = 16; o; o >>= 1) s += __shfl_down_sync(0xffffffffu, s, o);
    return s;
}

// ---------------------------------------------------------------------------
// Setup: blocks 0..7 build tree structure + zero scratch (one per graph).
// Blocks 8..39: warp-per-node base embeddings base[n] = vecs[data[n]]@dW + db.
// The warp owning node==pos also computes d_score = sbias + base[pos].sdw.
// ---------------------------------------------------------------------------
__global__ __launch_bounds__(128) void k_setup(
        const int* __restrict__ graphs, const int* __restrict__ edges,
        const int* __restrict__ posp,   const int* __restrict__ data,
        const float* __restrict__ vecs, const float* __restrict__ dW,
        const float* __restrict__ db,   const float* __restrict__ sdw,
        const float* __restrict__ sbias) {
    const int t = threadIdx.x;
    const int pos = posp[0];
    if (blockIdx.x < NG) {
        const int g = blockIdx.x;
        g_ccount[g][t] = 0;
        g_cdone[g][t]  = 0;
        g_onpath[g][t] = 0;
        for (int n = 0; n < NN; ++n) g_vacc[g][n][t] = 0.f;
        if (g == 0) {
            g_edges_eff[t] = (t == pos) ? -1 : edges[t];
            if (t == 0) g_taskctr = 0;
        }
        __syncthreads();
        const int off = graphs[g * NN + t];
        const int par = (off == 0) ? -1 : (t + off);
        g_parent[g][t] = par;
        if (par >= 0) atomicAdd(&g_ccount[g][par], 1);
        if (t == 0) {
            int cur = pos, len = 0;
            while (len < NN) {
                g_path[g][len++] = cur;
                g_onpath[g][cur] = 1;
                const int o = graphs[g * NN + cur];
                if (o == 0) break;
                cur += o;
            }
            g_plen[g] = len;
        }
    } else {
        __shared__ __align__(16) float shv[4][304];
        const int w = t >> 5, c = t & 31;
        const int n = (blockIdx.x - NG) * 4 + w;      // 32 blocks * 4 warps = 128 nodes
        const float* v = vecs + (long long)data[n] * VEC;
        for (int i = c; i < 304; i += 32) shv[w][i] = (i < VEC) ? v[i] : 0.f;
        __syncwarp();
        const int d0 = c * 4;
        float4 m = *(const float4*)(db + d0);
        mv_stream<VEC>((const float4*)(dW + d0), shv[w], m);
        *(float4*)&g_base[n][d0] = m;
        if (n == pos) {
            const float4 s4 = *(const float4*)(sdw + d0);
            const float s = warp_sum(m.x * s4.x + m.y * s4.y + m.z * s4.z + m.w * s4.w);
            if (c == 0) g_dscore = sbias[0] + s;
        }
    }
}

// ---------------------------------------------------------------------------
// Vector phase: persistent warp-level task workers. Task id = n*NG + g
// (topological: parents have higher node index). Each warp: grab task,
// prefetch its W matrix into L1 (overlaps the child-wait spin), spin on the
// child done-counter, finalize the vector, then either store it (path node)
// or matvec-transform and atomically add into the parent's accumulator.
// Grid (128 blocks) <= SM count so all workers are co-resident.
// ---------------------------------------------------------------------------
__global__ __launch_bounds__(128) void k_vector(const float* __restrict__ ew,
                                                const float* __restrict__ ebias) {
    __shared__ __align__(16) float shr[4][DIM];
    __shared__ int sh_task[4];
    const int w = threadIdx.x >> 5, c = threadIdx.x & 31;
    const int d0 = c * 4;
    while (true) {
        if (c == 0) sh_task[w] = atomicAdd(&g_taskctr, 1);
        __syncwarp();
        const int task = sh_task[w];
        if (task >= NG * NN) return;
        const int n = task >> 3;
        const int g = task & 7;
        const int need   = g_ccount[g][n];
        const int par    = g_parent[g][n];
        const int onpath = g_onpath[g][n];
        const int eid    = g_edges_eff[n];
        const float* W = ew + (long long)eid * DIM * DIM;
        if (!onpath) {
            // warm L1 with this task's 64KB weight matrix while waiting
            const char* wb = (const char*)W;
#pragma unroll
            for (int i = 0; i < 16; ++i)
                asm volatile("prefetch.global.L1 [%0];" :: "l"(wb + ((c + (i << 5)) << 7)));
        }
        if (c == 0) {
            volatile int* cd = &g_cdone[g][n];
            while (*cd < need) { }
        }
        __syncwarp();
        __threadfence();
        const float4 bs = *(const float4*)&g_base[n][d0];
        const float4 va = __ldcg((const float4*)&g_vacc[g][n][d0]);
        float4 v = make_float4(bs.x + va.x, bs.y + va.y, bs.z + va.z, bs.w + va.w);
        if (onpath) {
            *(float4*)&g_bvec[g][n][d0] = v;
            __threadfence();
            __syncwarp();
            if (c == 0 && par >= 0) atomicAdd(&g_cdone[g][par], 1);
        } else {
            if (need > 0) {  // relu only for internal nodes
                v.x = fmaxf(v.x, 0.f); v.y = fmaxf(v.y, 0.f);
                v.z = fmaxf(v.z, 0.f); v.w = fmaxf(v.w, 0.f);
            }
            *(float4*)&shr[w][d0] = v;
            __syncwarp();
            float4 m = *(const float4*)(ebias + eid * DIM + d0);
            mv_stream<DIM>((const float4*)(W + d0), shr[w], m);
            float* dst = &g_vacc[g][par][d0];
            atomicAdd(dst + 0, m.x); atomicAdd(dst + 1, m.y);
            atomicAdd(dst + 2, m.z); atomicAdd(dst + 3, m.w);
            __threadfence();
            __syncwarp();
            if (c == 0) atomicAdd(&g_cdone[g][par], 1);
        }
    }
}

// ---------------------------------------------------------------------------
// Matrix phase: warp-per-edge-row chains. Block = (graph, 8 rows); warp w
// owns row e and walks the pos->root path:
//   step 0: m_e = relu?(v[pos]) @ W[e] + b[e]   (per-row weights)
//   step s: m_e = relu(bvec[a_s] + m_e) @ W[edges[a_s]] + b
//   score  = d_score + m_e . sew
// After the one block sync for r0, warps run fully independently; the 8 warps
// of an SM share each step's W matrix through L1.
// ---------------------------------------------------------------------------
__global__ __launch_bounds__(256) void k_matrix(const float* __restrict__ ew,
                                                const float* __restrict__ ebias,
                                                const float* __restrict__ sew,
                                                float* __restrict__ out) {
    __shared__ __align__(16) float sh0[DIM];
    __shared__ __align__(16) float shr[8][DIM];
    const int t = threadIdx.x;
    const int w = t >> 5, c = t & 31;
    const int d0 = c * 4;
    const int g  = blockIdx.x >> 4;
    const int e  = (blockIdx.x & 15) * 8 + w;
    const int plen = g_plen[g];
    const int p0   = g_path[g][0];

    if (w == 0) {
        float4 v = *(const float4*)&g_bvec[g][p0][d0];
        if (g_ccount[g][p0] > 0) {
            v.x = fmaxf(v.x, 0.f); v.y = fmaxf(v.y, 0.f);
            v.z = fmaxf(v.z, 0.f); v.w = fmaxf(v.w, 0.f);
        }
        *(float4*)&sh0[d0] = v;
    }
    __syncthreads();

    // step 0: per-row weight matrix W[e]
    float4 m = *(const float4*)(ebias + e * DIM + d0);
    mv_stream<DIM>((const float4*)(ew + (long long)e * DIM * DIM + d0), sh0, m);

    // steps 1..plen-1: shared weight matrix per (graph, step)
    for (int s = 1; s < plen; ++s) {
        const int a = g_path[g][s];
        const float4 bv = *(const float4*)&g_bvec[g][a][d0];
        float4 r = make_float4(fmaxf(bv.x + m.x, 0.f), fmaxf(bv.y + m.y, 0.f),
                               fmaxf(bv.z + m.z, 0.f), fmaxf(bv.w + m.w, 0.f));
        *(float4*)&shr[w][d0] = r;
        __syncwarp();
        const int eid = g_edges_eff[a];
        m = *(const float4*)(ebias + eid * DIM + d0);
        mv_stream<DIM>((const float4*)(ew + (long long)eid * DIM * DIM + d0), shr[w], m);
        __syncwarp();
    }

    const float4 s4 = *(const float4*)(sew + d0);
    const float s = warp_sum(m.x * s4.x + m.y * s4.y + m.z * s4.z + m.w * s4.w);
    if (c == 0) out[g * NE + e] = g_dscore + s;
}

extern "C" void kernel_launch(void* const* d_in, const int* in_sizes, int n_in,
                              void* d_out, int out_size) {
    const int*   data   = (const int*)d_in[0];
    // d_in[1] = types (unused: single data_type)
    const int*   graphs = (const int*)d_in[2];
    const int*   edges  = (const int*)d_in[3];
    const int*   posp   = (const int*)d_in[4];
    const float* vecs   = (const float*)d_in[5];
    const float* dW     = (const float*)d_in[6];
    const float* db     = (const float*)d_in[7];
    const float* ew     = (const float*)d_in[8];
    const float* ebias  = (const float*)d_in[9];
    const float* sew    = (const float*)d_in[10];
    const float* sdw    = (const float*)d_in[11];
    const float* sbias  = (const float*)d_in[12];
    float* out = (float*)d_out;

    k_setup<<<NG + 32, 128>>>(graphs, edges, posp, data, vecs, dW, db, sdw, sbias);
    k_vector<<<128, 128>>>(ew, ebias);
    k_matrix<<<128, 256>>>(ew, ebias, sew, out);
}

// round 3
// speedup vs baseline: 2.4136x; 2.4136x over previous
#include <cuda_runtime.h>

#define NG  8     // graphs
#define NN  128   // nodes
#define DIM 128   // embedding dim
#define NE  128   // edge types
#define VEC 300   // word-vec dim
#define CHM 8     // k-chunk per double-buffer stage (float4 per k)

// ---- scratch (device globals; no allocations allowed) ----
__device__ __align__(16) float g_base[NN][DIM];
__device__ __align__(16) float g_vacc[NG][NN][DIM];
__device__ __align__(16) float g_bvec[NG][NN][DIM];
__device__ int   g_parent[NG][NN];
__device__ int   g_ccount[NG][NN];
__device__ int   g_cdone[NG][NN];
__device__ int   g_onpath[NG][NN];
__device__ int   g_path[NG][NN];
__device__ int   g_plen[NG];
__device__ int   g_edges_eff[NN];
__device__ float g_dscore;
__device__ int   g_taskctr;

// ---------------------------------------------------------------------------
// Streaming matvec: thread owns 4 consecutive output dims (d0 = 4*lane).
// W4 points at W[0][d0] (row stride DIM floats). Double-buffered register
// chunks -> 16 LDG.128 in flight per thread. REQUIRES a >=128-reg budget
// (launch_bounds(...,1)) or ptxas collapses the pipeline to MLP~2.
// ---------------------------------------------------------------------------
template<int K>
__device__ __forceinline__ void mv_stream(const float4* __restrict__ W4,
                                          const float* __restrict__ r,
                                          float4& m) {
    constexpr int STEP = 2 * CHM;
    constexpr int NCH  = (K + STEP - 1) / STEP;
    float4 A[CHM], B[CHM];
#pragma unroll
    for (int i = 0; i < CHM; ++i)
        A[i] = (i < K) ? W4[i * (DIM / 4)] : make_float4(0.f, 0.f, 0.f, 0.f);
#pragma unroll
    for (int o = 0; o < NCH; ++o) {
        const int kb = o * STEP, k2 = kb + CHM, k3 = kb + STEP;
#pragma unroll
        for (int i = 0; i < CHM; ++i)
            B[i] = (k2 + i < K) ? W4[(k2 + i) * (DIM / 4)] : make_float4(0.f, 0.f, 0.f, 0.f);
#pragma unroll
        for (int i = 0; i < CHM; ++i)
            if (kb + i < K) {
                const float rk = r[kb + i];
                m.x += rk * A[i].x; m.y += rk * A[i].y;
                m.z += rk * A[i].z; m.w += rk * A[i].w;
            }
#pragma unroll
        for (int i = 0; i < CHM; ++i)
            A[i] = (k3 + i < K) ? W4[(k3 + i) * (DIM / 4)] : make_float4(0.f, 0.f, 0.f, 0.f);
#pragma unroll
        for (int i = 0; i < CHM; ++i)
            if (k2 + i < K) {
                const float rk = r[k2 + i];
                m.x += rk * B[i].x; m.y += rk * B[i].y;
                m.z += rk * B[i].z; m.w += rk * B[i].w;
            }
    }
}

__device__ __forceinline__ float warp_sum(float s) {
#pragma unroll
    for (int o = 16; o; o >>= 1) s += __shfl_down_sync(0xffffffffu, s, o);
    return s;
}

// ---------------------------------------------------------------------------
// Setup: blocks 0..7 build tree structure + zero scratch (one per graph).
// Blocks 8..39: warp-per-node base embeddings base[n] = vecs[data[n]]@dW + db.
// The warp owning node==pos also computes d_score = sbias + base[pos].sdw.
// ---------------------------------------------------------------------------
__global__ __launch_bounds__(128, 1) void k_setup(
        const int* __restrict__ graphs, const int* __restrict__ edges,
        const int* __restrict__ posp,   const int* __restrict__ data,
        const float* __restrict__ vecs, const float* __restrict__ dW,
        const float* __restrict__ db,   const float* __restrict__ sdw,
        const float* __restrict__ sbias) {
    const int t = threadIdx.x;
    const int pos = posp[0];
    if (blockIdx.x < NG) {
        const int g = blockIdx.x;
        g_ccount[g][t] = 0;
        g_cdone[g][t]  = 0;
        g_onpath[g][t] = 0;
        for (int n = 0; n < NN; ++n) g_vacc[g][n][t] = 0.f;
        if (g == 0) {
            g_edges_eff[t] = (t == pos) ? -1 : edges[t];
            if (t == 0) g_taskctr = 0;
        }
        __syncthreads();
        const int off = graphs[g * NN + t];
        const int par = (off == 0) ? -1 : (t + off);
        g_parent[g][t] = par;
        if (par >= 0) atomicAdd(&g_ccount[g][par], 1);
        if (t == 0) {
            int cur = pos, len = 0;
            while (len < NN) {
                g_path[g][len++] = cur;
                g_onpath[g][cur] = 1;
                const int o = graphs[g * NN + cur];
                if (o == 0) break;
                cur += o;
            }
            g_plen[g] = len;
        }
    } else {
        __shared__ __align__(16) float shv[4][304];
        const int w = t >> 5, c = t & 31;
        const int n = (blockIdx.x - NG) * 4 + w;      // 32 blocks * 4 warps = 128 nodes
        const float* v = vecs + (long long)data[n] * VEC;
        for (int i = c; i < 304; i += 32) shv[w][i] = (i < VEC) ? v[i] : 0.f;
        __syncwarp();
        const int d0 = c * 4;
        float4 m = *(const float4*)(db + d0);
        mv_stream<VEC>((const float4*)(dW + d0), shv[w], m);
        *(float4*)&g_base[n][d0] = m;
        if (n == pos) {
            const float4 s4 = *(const float4*)(sdw + d0);
            const float s = warp_sum(m.x * s4.x + m.y * s4.y + m.z * s4.z + m.w * s4.w);
            if (c == 0) g_dscore = sbias[0] + s;
        }
    }
}

// ---------------------------------------------------------------------------
// Vector phase: persistent warp-level task workers. Task id = n*NG + g
// (topological: parents have higher node index). Each warp: grab task,
// prefetch its W matrix into L1 (overlaps the child-wait spin), spin on the
// child done-counter, finalize the vector, then either store it (path node)
// or matvec-transform and atomically add into the parent's accumulator.
// Grid (128 blocks, 1/SM) <= SM count so all workers are co-resident.
// ---------------------------------------------------------------------------
__global__ __launch_bounds__(128, 1) void k_vector(const float* __restrict__ ew,
                                                   const float* __restrict__ ebias) {
    __shared__ __align__(16) float shr[4][DIM];
    __shared__ int sh_task[4];
    const int w = threadIdx.x >> 5, c = threadIdx.x & 31;
    const int d0 = c * 4;
    while (true) {
        if (c == 0) sh_task[w] = atomicAdd(&g_taskctr, 1);
        __syncwarp();
        const int task = sh_task[w];
        if (task >= NG * NN) return;
        const int n = task >> 3;
        const int g = task & 7;
        const int need   = g_ccount[g][n];
        const int par    = g_parent[g][n];
        const int onpath = g_onpath[g][n];
        const int eid    = g_edges_eff[n];
        const float* W = ew + (long long)eid * DIM * DIM;
        if (!onpath) {
            // warm L1 with this task's 64KB weight matrix while waiting
            const char* wb = (const char*)W;
#pragma unroll
            for (int i = 0; i < 16; ++i)
                asm volatile("prefetch.global.L1 [%0];" :: "l"(wb + ((c + (i << 5)) << 7)));
        }
        if (c == 0) {
            volatile int* cd = &g_cdone[g][n];
            while (*cd < need) { }
        }
        __syncwarp();
        __threadfence();
        const float4 bs = *(const float4*)&g_base[n][d0];
        const float4 va = __ldcg((const float4*)&g_vacc[g][n][d0]);
        float4 v = make_float4(bs.x + va.x, bs.y + va.y, bs.z + va.z, bs.w + va.w);
        if (onpath) {
            *(float4*)&g_bvec[g][n][d0] = v;
            __threadfence();
            __syncwarp();
            if (c == 0 && par >= 0) atomicAdd(&g_cdone[g][par], 1);
        } else {
            if (need > 0) {  // relu only for internal nodes
                v.x = fmaxf(v.x, 0.f); v.y = fmaxf(v.y, 0.f);
                v.z = fmaxf(v.z, 0.f); v.w = fmaxf(v.w, 0.f);
            }
            *(float4*)&shr[w][d0] = v;
            __syncwarp();
            float4 m = *(const float4*)(ebias + eid * DIM + d0);
            mv_stream<DIM>((const float4*)(W + d0), shr[w], m);
            float* dst = &g_vacc[g][par][d0];
            atomicAdd(dst + 0, m.x); atomicAdd(dst + 1, m.y);
            atomicAdd(dst + 2, m.z); atomicAdd(dst + 3, m.w);
            __threadfence();
            __syncwarp();
            if (c == 0) atomicAdd(&g_cdone[g][par], 1);
        }
    }
}

// ---------------------------------------------------------------------------
// Matrix phase: warp-per-edge-row chains. Block = (graph, 8 rows); warp w
// owns row e and walks the pos->root path:
//   step 0: m_e = relu?(v[pos]) @ W[e] + b[e]   (per-row weights)
//   step s: m_e = relu(bvec[a_s] + m_e) @ W[edges[a_s]] + b
//   score  = d_score + m_e . sew
// After the one block sync for r0, warps run fully independently; the 8 warps
// of an SM share each step's W matrix through L1/L2.
// ---------------------------------------------------------------------------
__global__ __launch_bounds__(256, 1) void k_matrix(const float* __restrict__ ew,
                                                   const float* __restrict__ ebias,
                                                   const float* __restrict__ sew,
                                                   float* __restrict__ out) {
    __shared__ __align__(16) float sh0[DIM];
    __shared__ __align__(16) float shr[8][DIM];
    const int t = threadIdx.x;
    const int w = t >> 5, c = t & 31;
    const int d0 = c * 4;
    const int g  = blockIdx.x >> 4;
    const int e  = (blockIdx.x & 15) * 8 + w;
    const int plen = g_plen[g];
    const int p0   = g_path[g][0];

    if (w == 0) {
        float4 v = *(const float4*)&g_bvec[g][p0][d0];
        if (g_ccount[g][p0] > 0) {
            v.x = fmaxf(v.x, 0.f); v.y = fmaxf(v.y, 0.f);
            v.z = fmaxf(v.z, 0.f); v.w = fmaxf(v.w, 0.f);
        }
        *(float4*)&sh0[d0] = v;
    }
    __syncthreads();

    // step 0: per-row weight matrix W[e]
    float4 m = *(const float4*)(ebias + e * DIM + d0);
    mv_stream<DIM>((const float4*)(ew + (long long)e * DIM * DIM + d0), sh0, m);

    // steps 1..plen-1: shared weight matrix per (graph, step)
    for (int s = 1; s < plen; ++s) {
        const int a = g_path[g][s];
        const float4 bv = *(const float4*)&g_bvec[g][a][d0];
        float4 r = make_float4(fmaxf(bv.x + m.x, 0.f), fmaxf(bv.y + m.y, 0.f),
                               fmaxf(bv.z + m.z, 0.f), fmaxf(bv.w + m.w, 0.f));
        *(float4*)&shr[w][d0] = r;
        __syncwarp();
        const int eid = g_edges_eff[a];
        m = *(const float4*)(ebias + eid * DIM + d0);
        mv_stream<DIM>((const float4*)(ew + (long long)eid * DIM * DIM + d0), shr[w], m);
        __syncwarp();
    }

    const float4 s4 = *(const float4*)(sew + d0);
    const float s = warp_sum(m.x * s4.x + m.y * s4.y + m.z * s4.z + m.w * s4.w);
    if (c == 0) out[g * NE + e] = g_dscore + s;
}

extern "C" void kernel_launch(void* const* d_in, const int* in_sizes, int n_in,
                              void* d_out, int out_size) {
    const int*   data   = (const int*)d_in[0];
    // d_in[1] = types (unused: single data_type)
    const int*   graphs = (const int*)d_in[2];
    const int*   edges  = (const int*)d_in[3];
    const int*   posp   = (const int*)d_in[4];
    const float* vecs   = (const float*)d_in[5];
    const float* dW     = (const float*)d_in[6];
    const float* db     = (const float*)d_in[7];
    const float* ew     = (const float*)d_in[8];
    const float* ebias  = (const float*)d_in[9];
    const float* sew    = (const float*)d_in[10];
    const float* sdw    = (const float*)d_in[11];
    const float* sbias  = (const float*)d_in[12];
    float* out = (float*)d_out;

    k_setup<<<NG + 32, 128>>>(graphs, edges, posp, data, vecs, dW, db, sdw, sbias);
    k_vector<<<128, 128>>>(ew, ebias);
    k_matrix<<<128, 256>>>(ew, ebias, sew, out);
}

// round 5
// speedup vs baseline: 3.9365x; 1.6310x over previous
#include <cuda_runtime.h>

#define NG  8     // graphs
#define NN  128   // nodes
#define DIM 128   // embedding dim
#define NE  128   // edge types
#define VEC 300   // word-vec dim

// ---- scratch (device globals; no allocations allowed) ----
__device__ __align__(16) float g_base[NN][DIM];
__device__ __align__(16) float g_vacc[NG][NN][DIM];
__device__ __align__(16) float g_bvec[NG][NN][DIM];
__device__ int   g_parent[NG][NN];
__device__ int   g_ccount[NG][NN];
__device__ int   g_cdone[NG][NN];
__device__ int   g_onpath[NG][NN];
__device__ int   g_path[NG][NN];
__device__ int   g_plen[NG];
__device__ int   g_edges_eff[NN];
__device__ int   g_rootdone[NG];
__device__ float g_dscore;

// ---- acquire/release primitives ----
__device__ __forceinline__ int ld_acquire(const int* p) {
    int v;
    asm volatile("ld.acquire.gpu.global.u32 %0, [%1];" : "=r"(v) : "l"(p) : "memory");
    return v;
}
__device__ __forceinline__ void red_release_add(int* p, int v) {
    asm volatile("red.release.gpu.global.add.u32 [%0], %1;" :: "l"(p), "r"(v) : "memory");
}
// ALL lanes spin (each lane carries its own acquire edge; same-address load
// broadcasts, so a poll costs one wavefront). Formal HB to every lane.
__device__ __forceinline__ void wait_ge(const int* p, int need) {
    while (ld_acquire(p) < need) { }
    __syncwarp();
}

// ---------------------------------------------------------------------------
// Streaming matvec: thread owns 4 consecutive output dims (d0 = 4*lane).
// W4 points at W[0][d0] (row stride DIM floats). Double-buffered register
// chunks -> 2*CH LDG.128 in flight per thread (needs launch_bounds(...,1)).
// ---------------------------------------------------------------------------
template<int K, int CH>
__device__ __forceinline__ void mv_stream(const float4* __restrict__ W4,
                                          const float* __restrict__ r,
                                          float4& m) {
    constexpr int STEP = 2 * CH;
    constexpr int NCH  = (K + STEP - 1) / STEP;
    float4 A[CH], B[CH];
#pragma unroll
    for (int i = 0; i < CH; ++i)
        A[i] = (i < K) ? W4[i * (DIM / 4)] : make_float4(0.f, 0.f, 0.f, 0.f);
#pragma unroll
    for (int o = 0; o < NCH; ++o) {
        const int kb = o * STEP, k2 = kb + CH, k3 = kb + STEP;
#pragma unroll
        for (int i = 0; i < CH; ++i)
            B[i] = (k2 + i < K) ? W4[(k2 + i) * (DIM / 4)] : make_float4(0.f, 0.f, 0.f, 0.f);
#pragma unroll
        for (int i = 0; i < CH; ++i)
            if (kb + i < K) {
                const float rk = r[kb + i];
                m.x += rk * A[i].x; m.y += rk * A[i].y;
                m.z += rk * A[i].z; m.w += rk * A[i].w;
            }
#pragma unroll
        for (int i = 0; i < CH; ++i)
            A[i] = (k3 + i < K) ? W4[(k3 + i) * (DIM / 4)] : make_float4(0.f, 0.f, 0.f, 0.f);
#pragma unroll
        for (int i = 0; i < CH; ++i)
            if (k2 + i < K) {
                const float rk = r[k2 + i];
                m.x += rk * B[i].x; m.y += rk * B[i].y;
                m.z += rk * B[i].z; m.w += rk * B[i].w;
            }
    }
}

__device__ __forceinline__ float warp_sum(float s) {
#pragma unroll
    for (int o = 16; o; o >>= 1) s += __shfl_down_sync(0xffffffffu, s, o);
    return s;
}

__device__ __forceinline__ float4 relu4(float4 v) {
    return make_float4(fmaxf(v.x, 0.f), fmaxf(v.y, 0.f), fmaxf(v.z, 0.f), fmaxf(v.w, 0.f));
}

// ---------------------------------------------------------------------------
// Setup. Blocks 0..7: tree structure + scratch reset for one graph each.
// Blocks 8..135: one node each; 4-warp k-split of the VEC=300 matvec
//   base[n] = vecs[data[n]] @ dW + db. The block owning n==pos also emits
//   d_score = sbias + base[pos].sdw.
// ---------------------------------------------------------------------------
__global__ __launch_bounds__(128, 1) void k_setup(
        const int* __restrict__ graphs, const int* __restrict__ edges,
        const int* __restrict__ posp,   const int* __restrict__ data,
        const float* __restrict__ vecs, const float* __restrict__ dW,
        const float* __restrict__ db,   const float* __restrict__ sdw,
        const float* __restrict__ sbias) {
    const int t = threadIdx.x;
    const int pos = posp[0];
    if (blockIdx.x < NG) {
        const int g = blockIdx.x;
        g_ccount[g][t] = 0;
        g_cdone[g][t]  = 0;
        g_onpath[g][t] = 0;
        for (int n = 0; n < NN; ++n) g_vacc[g][n][t] = 0.f;
        if (g == 0) g_edges_eff[t] = (t == pos) ? -1 : edges[t];
        if (t == 0) g_rootdone[g] = 0;
        __syncthreads();
        const int off = graphs[g * NN + t];
        const int par = (off == 0) ? -1 : (t + off);
        g_parent[g][t] = par;
        if (par >= 0) atomicAdd(&g_ccount[g][par], 1);
        if (t == 0) {
            int cur = pos, len = 0;
            while (len < NN) {
                g_path[g][len++] = cur;
                g_onpath[g][cur] = 1;
                const int o = graphs[g * NN + cur];
                if (o == 0) break;
                cur += o;
            }
            g_plen[g] = len;
        }
    } else {
        __shared__ __align__(16) float shv[304];
        __shared__ __align__(16) float4 part[4][32];
        const int n = blockIdx.x - NG;
        const int w = t >> 5, c = t & 31, d0 = c * 4;
        const float* vr = vecs + (long long)data[n] * VEC;
        for (int i = t; i < VEC; i += 128) shv[i] = vr[i];
        __syncthreads();
        const int k0 = w * 75;                 // 4 * 75 = 300 exact
        float4 acc = make_float4(0.f, 0.f, 0.f, 0.f);
        mv_stream<75, 8>((const float4*)(dW + (long long)k0 * DIM + d0), shv + k0, acc);
        part[w][c] = acc;
        __syncthreads();
        if (w == 0) {
            float4 m = *(const float4*)(db + d0);
#pragma unroll
            for (int ww = 0; ww < 4; ++ww) {
                const float4 p = part[ww][c];
                m.x += p.x; m.y += p.y; m.z += p.z; m.w += p.w;
            }
            *(float4*)&g_base[n][d0] = m;
            if (n == pos) {
                const float4 s4 = *(const float4*)(sdw + d0);
                const float s = warp_sum(m.x * s4.x + m.y * s4.y + m.z * s4.z + m.w * s4.w);
                if (c == 0) g_dscore = sbias[0] + s;
            }
        }
    }
}

// ---------------------------------------------------------------------------
// Fused main kernel: 128 blocks x 8 warps = 1024 resident warps (1 block/SM,
// 128 <= 148 SMs -> all producers co-resident; spins cannot deadlock).
// Phase 1 (vector): warp (block=n, warp=g) owns tree task (n,g). Wait for the
//   child done-counter (all-lane acquire), finalize the node vector, then
//   either store it (pos->root path node) or matvec-transform and atomic-add
//   into the parent accumulator; signal with release-add.
// Phase 2 (matrix): warp (g=block>>4, row e=(block&15)*8+w) waits on the
//   graph's rootdone flag, then walks the pos->root chain of matvecs for its
//   edge row and emits the score. Early graphs overlap late vector work.
// ---------------------------------------------------------------------------
__global__ __launch_bounds__(256, 1) void k_main(const float* __restrict__ ew,
                                                 const float* __restrict__ ebias,
                                                 const float* __restrict__ sew,
                                                 float* __restrict__ out) {
    __shared__ __align__(16) float shr[8][DIM];
    const int t = threadIdx.x;
    const int w = t >> 5, c = t & 31;
    const int d0 = c * 4;

    // ---------------- phase 1: vector task (n = block, g = warp) ----------
    {
        const int n = blockIdx.x;
        const int g = w;
        const int need   = g_ccount[g][n];
        const int par    = g_parent[g][n];
        const int onpath = g_onpath[g][n];
        const int eid    = g_edges_eff[n];
        const float* W = ew + (long long)eid * DIM * DIM;
        if (!onpath && need > 0) {
            // pull this task's weights toward L2 while waiting
            const char* wb = (const char*)W;
#pragma unroll
            for (int i = 0; i < 16; ++i)
                asm volatile("prefetch.global.L2 [%0];" :: "l"(wb + ((c + (i << 5)) << 7)));
        }
        if (need > 0) wait_ge(&g_cdone[g][n], need);
        float4 v = *(const float4*)&g_base[n][d0];
        if (need > 0) {
            const float4 va = __ldcg((const float4*)&g_vacc[g][n][d0]);
            v.x += va.x; v.y += va.y; v.z += va.z; v.w += va.w;
        }
        if (onpath) {
            *(float4*)&g_bvec[g][n][d0] = v;
            __syncwarp();
            if (c == 0) {
                if (par >= 0) red_release_add(&g_cdone[g][par], 1);
                else          red_release_add(&g_rootdone[g], 1);
            }
        } else {
            if (need > 0) v = relu4(v);       // relu only for internal nodes
            *(float4*)&shr[w][d0] = v;
            __syncwarp();
            float4 m = *(const float4*)(ebias + eid * DIM + d0);
            mv_stream<DIM, 16>((const float4*)(W + d0), shr[w], m);
            float* dst = &g_vacc[g][par][d0];
            atomicAdd(dst + 0, m.x); atomicAdd(dst + 1, m.y);
            atomicAdd(dst + 2, m.z); atomicAdd(dst + 3, m.w);
            __syncwarp();
            if (c == 0) red_release_add(&g_cdone[g][par], 1);
        }
        __syncwarp();
    }

    // ---------------- phase 2: matrix chain (g = block>>4, row e) ----------
    {
        const int g = blockIdx.x >> 4;
        const int e = (blockIdx.x & 15) * 8 + w;
        {
            // warm L2 with this row's step-0 weights while waiting
            const char* wb = (const char*)(ew + (long long)e * DIM * DIM);
#pragma unroll
            for (int i = 0; i < 16; ++i)
                asm volatile("prefetch.global.L2 [%0];" :: "l"(wb + ((c + (i << 5)) << 7)));
        }
        wait_ge(&g_rootdone[g], 1);

        const int plen = g_plen[g];
        const int p0   = g_path[g][0];

        float4 r0 = __ldcg((const float4*)&g_bvec[g][p0][d0]);
        if (g_ccount[g][p0] > 0) r0 = relu4(r0);
        *(float4*)&shr[w][d0] = r0;
        __syncwarp();

        // step 0: per-row weight matrix W[e]
        float4 m = *(const float4*)(ebias + e * DIM + d0);
        mv_stream<DIM, 16>((const float4*)(ew + (long long)e * DIM * DIM + d0), shr[w], m);

        // steps 1..plen-1: shared weight matrix per (graph, step)
        for (int s = 1; s < plen; ++s) {
            const int a = g_path[g][s];
            const float4 bv = __ldcg((const float4*)&g_bvec[g][a][d0]);
            const float4 r = make_float4(fmaxf(bv.x + m.x, 0.f), fmaxf(bv.y + m.y, 0.f),
                                         fmaxf(bv.z + m.z, 0.f), fmaxf(bv.w + m.w, 0.f));
            __syncwarp();                      // all lanes done reading prior shr
            *(float4*)&shr[w][d0] = r;
            __syncwarp();
            const int eid = g_edges_eff[a];
            m = *(const float4*)(ebias + eid * DIM + d0);
            mv_stream<DIM, 16>((const float4*)(ew + (long long)eid * DIM * DIM + d0), shr[w], m);
        }

        const float4 s4 = *(const float4*)(sew + d0);
        const float s = warp_sum(m.x * s4.x + m.y * s4.y + m.z * s4.z + m.w * s4.w);
        if (c == 0) out[g * NE + e] = g_dscore + s;
    }
}

extern "C" void kernel_launch(void* const* d_in, const int* in_sizes, int n_in,
                              void* d_out, int out_size) {
    const int*   data   = (const int*)d_in[0];
    // d_in[1] = types (unused: single data_type)
    const int*   graphs = (const int*)d_in[2];
    const int*   edges  = (const int*)d_in[3];
    const int*   posp   = (const int*)d_in[4];
    const float* vecs   = (const float*)d_in[5];
    const float* dW     = (const float*)d_in[6];
    const float* db     = (const float*)d_in[7];
    const float* ew     = (const float*)d_in[8];
    const float* ebias  = (const float*)d_in[9];
    const float* sew    = (const float*)d_in[10];
    const float* sdw    = (const float*)d_in[11];
    const float* sbias  = (const float*)d_in[12];
    float* out = (float*)d_out;

    k_setup<<<NG + NN, 128>>>(graphs, edges, posp, data, vecs, dW, db, sdw, sbias);
    k_main<<<128, 256>>>(ew, ebias, sew, out);
}